// round 17
// baseline (speedup 1.0000x reference)
#include <cuda_runtime.h>
#include <cuda_fp16.h>
#include <math.h>
#include <stdint.h>

// ---------------- problem constants ----------------
#define CC     10
#define NCLUST 11            // C+1
#define NSEG   88            // B * (C+1)
#define BATCH  8
#define NPB    16384         // tokens per batch
#define MTOT   131072        // B*N
#define IDIM   512
#define EMBD   8
#define DDIM   256

// ---------------- scratch (static device globals) ----------------
__device__ __half g_x16[(size_t)MTOT * IDIM];    // fused features in fp16
__device__ __half g_Wf16[IDIM * IDIM];           // W_fuse[0:512] transposed [n][k]
__device__ __half g_Wa16[DDIM * IDIM];           // Wa1 transposed [d][k]
__device__ __half g_Wb16[DDIM * IDIM];           // Wb1 transposed [d][k]
__device__ float  g_embW[NCLUST * IDIM];         // bias + emb@Wfuse[512:520] per (cid, n)
__device__ float  g_A[MTOT];                     // intra logits (bc1 dropped: softmax-invariant)
__device__ float  g_ex[MTOT];
__device__ float  g_segsum[NSEG];
__device__ int    g_counts[NSEG];
__device__ float  g_cfraw[NSEG * IDIM];
__device__ float  g_cfeat[NSEG * IDIM];
__device__ float  g_A2[NSEG];

// ---------------- helpers ----------------
__device__ __forceinline__ float sigmoidf_(float v) { return 1.0f / (1.0f + expf(-v)); }

__device__ __forceinline__ uint32_t smem_u32(const void* p) {
    return (uint32_t)__cvta_generic_to_shared(p);
}
__device__ __forceinline__ void cp16(uint32_t dst, const void* src) {
    asm volatile("cp.async.cg.shared.global [%0], [%1], 16;" :: "r"(dst), "l"(src));
}
#define CP_COMMIT()  asm volatile("cp.async.commit_group;")
#define CP_WAIT2()   asm volatile("cp.async.wait_group 2;")
#define CP_WAIT1()   asm volatile("cp.async.wait_group 1;")
#define CP_WAIT0()   asm volatile("cp.async.wait_group 0;")

// m16n8k16 fp16 mma, row.col, fp32 accum
__device__ __forceinline__ void mma_f16(float* d, const uint32_t* a, const uint32_t* b) {
    asm volatile(
        "mma.sync.aligned.m16n8k16.row.col.f32.f16.f16.f32 "
        "{%0,%1,%2,%3}, {%4,%5,%6,%7}, {%8,%9}, {%0,%1,%2,%3};\n"
        : "+f"(d[0]), "+f"(d[1]), "+f"(d[2]), "+f"(d[3])
        : "r"(a[0]), "r"(a[1]), "r"(a[2]), "r"(a[3]), "r"(b[0]), "r"(b[1]));
}

// ldmatrix x4 (non-trans): 4 m8n8 b16 tiles
__device__ __forceinline__ void ldsm_x4(uint32_t* r, uint32_t addr) {
    asm volatile("ldmatrix.sync.aligned.m8n8.x4.shared.b16 {%0,%1,%2,%3}, [%4];"
                 : "=r"(r[0]), "=r"(r[1]), "=r"(r[2]), "=r"(r[3]) : "r"(addr));
}

// fp16 smem geometry: rows padded to 40 halves (80 B)
#define ROW_H   40
#define ROW_B   80
// attn1 stage (unchanged from R15)
#define STAGE_B 20480
#define A_DSMEM (4 * STAGE_B)
// fuse stages: Af32 (128 rows x 144 B) + B fp16 (128 x 80 B); single shared Af16 buffer
#define F_ST32   144
#define F_BOFF   18432
#define F_STAGE  (18432 + 10240)      // 28672
#define F_AF16_OFF (3 * F_STAGE)      // 86016
#define F_DSMEM  (3 * F_STAGE + 10240) // 96256

// ---------------- kernel 0: init + weight conversion + embW (merged) ----------------
__global__ void prep_all_kernel(const float* __restrict__ Wf, const float* __restrict__ bf,
                                const float* __restrict__ emb,
                                const float* __restrict__ Wa1, const float* __restrict__ Wb1) {
    int gtid = blockIdx.x * blockDim.x + threadIdx.x;
    int stride = gridDim.x * blockDim.x;
    for (int i = gtid; i < MTOT; i += stride) g_A[i] = 0.0f;
    for (int i = gtid; i < NSEG * IDIM; i += stride) g_cfraw[i] = 0.0f;
    if (gtid < NSEG) { g_segsum[gtid] = 0.0f; g_counts[gtid] = 0; }
    for (int i = gtid; i < IDIM * IDIM; i += stride) {
        int n = i >> 9, k = i & 511;
        g_Wf16[i] = __float2half_rn(Wf[(size_t)k * IDIM + n]);
    }
    for (int i = gtid; i < DDIM * IDIM; i += stride) {
        int d = i >> 9, k = i & 511;
        g_Wa16[i] = __float2half_rn(Wa1[(size_t)k * DDIM + d]);
        g_Wb16[i] = __float2half_rn(Wb1[(size_t)k * DDIM + d]);
    }
    for (int i = gtid; i < NCLUST * IDIM; i += stride) {
        int c = i >> 9, n = i & 511;
        float v = bf[n];
#pragma unroll
        for (int e = 0; e < EMBD; e++)
            v += emb[c * EMBD + e] * Wf[(size_t)(IDIM + e) * IDIM + n];
        g_embW[i] = v;
    }
}

// ---------------- kernel 1: x = relu([h | emb] @ W_fuse + b) ----------------
// Consumes f32 h DIRECTLY (no prep_h): cp.async f32 slab -> in-smem cvt to fp16 -> ldmatrix/mma.
// 256 threads (8 warps 2Mx4N), warp tile 64x32, BK=32, 3-stage f32+B ring + shared Af16 buffer.
__global__ __launch_bounds__(256, 2) void fuse_f16_kernel(
    const float* __restrict__ h, const int* __restrict__ cids) {
    extern __shared__ uint8_t dsm[];
    __shared__ float sEmbW[NCLUST * 128];
    __shared__ int   scids[128];

    const int tid  = threadIdx.x;
    const int n0   = blockIdx.x * 128;
    const int m0   = blockIdx.y * 128;
    const int warp = tid >> 5, lane = tid & 31;
    const int gid  = lane >> 2, tig = lane & 3;
    const int wm   = (warp >> 2) * 64;        // 2 M-groups of 64
    const int wn   = (warp & 3) * 32;         // 4 N-groups of 32
    const uint32_t ub = smem_u32(dsm);

    // ldmatrix lane addressing
    const int a_row = lane & 15;
    const int a_k   = (lane >> 4) << 3;                 // 0 | 8
    const int b_row = (lane & 7) + ((lane >> 4) << 3);  // n-row within 16
    const int b_k   = ((lane >> 3) & 1) << 3;           // 0 | 8

    if (tid < 128) { int c = cids[m0 + tid]; scids[tid] = min(max(c, 0), CC); }
    for (int t = tid; t < NCLUST * 128; t += 256) {
        int c = t >> 7, j = t & 127;
        sEmbW[t] = g_embW[c * IDIM + n0 + j];
    }

    float acc[4][4][4];     // 4 M16-tiles x 4 N8-tiles
#pragma unroll
    for (int mi = 0; mi < 4; mi++)
#pragma unroll
        for (int ni = 0; ni < 4; ni++)
#pragma unroll
            for (int c = 0; c < 4; c++) acc[mi][ni][c] = 0.0f;

    auto load_slab = [&](int kt) {
        const int st = kt % 3;
        const int k0 = kt * 32;
        const uint32_t sb = ub + st * F_STAGE;
#pragma unroll
        for (int i = 0; i < 4; i++) {                 // A f32: 128 rows x 8 chunks of 4 floats
            int idx = i * 256 + tid;
            int row = idx >> 3, ch = idx & 7;
            cp16(sb + row * F_ST32 + ch * 16,
                 h + (size_t)(m0 + row) * IDIM + k0 + ch * 4);
        }
#pragma unroll
        for (int i = 0; i < 2; i++) {                 // B fp16: 128 n-rows x 4 chunks
            int idx = i * 256 + tid;
            int row = idx >> 2, ch = idx & 3;
            cp16(sb + F_BOFF + row * ROW_B + ch * 16,
                 g_Wf16 + (size_t)(n0 + row) * IDIM + k0 + ch * 8);
        }
    };

    load_slab(0); CP_COMMIT();
    load_slab(1); CP_COMMIT();
    load_slab(2); CP_COMMIT();

    const int cvt_row = tid >> 1, cvt_hf = tid & 1;

    for (int kt = 0; kt < 16; kt++) {
        if (kt <= 13)      { CP_WAIT2(); }
        else if (kt == 14) { CP_WAIT1(); }
        else               { CP_WAIT0(); }
        __syncthreads();

        // in-smem cvt: Af32 (stage kt%3) -> shared Af16 buffer (2 threads/row, 16 f32 each)
        {
            const uint8_t* src = dsm + (kt % 3) * F_STAGE + cvt_row * F_ST32 + cvt_hf * 64;
            uint8_t*       dst = dsm + F_AF16_OFF + cvt_row * ROW_B + cvt_hf * 32;
            float4 v0 = ((const float4*)src)[0];
            float4 v1 = ((const float4*)src)[1];
            float4 v2 = ((const float4*)src)[2];
            float4 v3 = ((const float4*)src)[3];
            __half2 p0 = __floats2half2_rn(v0.x, v0.y), p1 = __floats2half2_rn(v0.z, v0.w);
            __half2 p2 = __floats2half2_rn(v1.x, v1.y), p3 = __floats2half2_rn(v1.z, v1.w);
            __half2 p4 = __floats2half2_rn(v2.x, v2.y), p5 = __floats2half2_rn(v2.z, v2.w);
            __half2 p6 = __floats2half2_rn(v3.x, v3.y), p7 = __floats2half2_rn(v3.z, v3.w);
            uint4 o0, o1;
            o0.x = *(uint32_t*)&p0; o0.y = *(uint32_t*)&p1;
            o0.z = *(uint32_t*)&p2; o0.w = *(uint32_t*)&p3;
            o1.x = *(uint32_t*)&p4; o1.y = *(uint32_t*)&p5;
            o1.z = *(uint32_t*)&p6; o1.w = *(uint32_t*)&p7;
            ((uint4*)dst)[0] = o0;
            ((uint4*)dst)[1] = o1;
        }
        __syncthreads();

        const uint32_t saf = ub + F_AF16_OFF;
        const uint32_t sbb = ub + (kt % 3) * F_STAGE + F_BOFF;
#pragma unroll
        for (int ks = 0; ks < 2; ks++) {
            uint32_t af[4][4], bfr[4][2];
#pragma unroll
            for (int mi = 0; mi < 4; mi++)
                ldsm_x4(af[mi], saf + (wm + mi * 16 + a_row) * ROW_B + (ks * 16 + a_k) * 2);
#pragma unroll
            for (int nj = 0; nj < 2; nj++)
                ldsm_x4(&bfr[2 * nj][0], sbb + (wn + nj * 16 + b_row) * ROW_B + (ks * 16 + b_k) * 2);
#pragma unroll
            for (int mi = 0; mi < 4; mi++)
#pragma unroll
                for (int ni = 0; ni < 4; ni++)
                    mma_f16(acc[mi][ni], af[mi], bfr[ni]);
        }
        __syncthreads();
        if (kt <= 12) { load_slab(kt + 3); CP_COMMIT(); }
    }

    // epilogue: + embW(cid,n) (bias+emb folded), relu, store fp16
#pragma unroll
    for (int mi = 0; mi < 4; mi++) {
#pragma unroll
        for (int half = 0; half < 2; half++) {
            int ml = wm + mi * 16 + gid + half * 8;
            int m  = m0 + ml;
            const float* ew = &sEmbW[scids[ml] * 128];
#pragma unroll
            for (int ni = 0; ni < 4; ni++) {
                int nl = wn + ni * 8 + 2 * tig;
                float o0 = fmaxf(acc[mi][ni][half * 2 + 0] + ew[nl],     0.0f);
                float o1 = fmaxf(acc[mi][ni][half * 2 + 1] + ew[nl + 1], 0.0f);
                *(__half2*)&g_x16[(size_t)m * IDIM + n0 + nl] = __floats2half2_rn(o0, o1);
            }
        }
    }
}

// ---------------- kernel 2: intra gated attention logits (dual fp16 mma, ldmatrix) ----------------
// 256 threads (8 warps 2Mx4D), warp tile 64 rows x 16 d, PAIRWISE slab compute. (R15, unchanged)
__global__ __launch_bounds__(256, 2) void attn1_f16_kernel(
    const float* __restrict__ ba1, const float* __restrict__ bb1,
    const float* __restrict__ Wc1) {
    extern __shared__ uint8_t dsm[];
    __shared__ float sba[64], sbb[64], swc[64];
    __shared__ float sA[128];

    const int tid  = threadIdx.x;
    const int d0   = blockIdx.x * 64;
    const int m0   = blockIdx.y * 128;
    const int warp = tid >> 5, lane = tid & 31;
    const int gid  = lane >> 2, tig = lane & 3;
    const int wm   = (warp >> 2) * 64;
    const int wn   = (warp & 3) * 16;
    const uint32_t ub = smem_u32(dsm);

    const int a_row = lane & 15;
    const int a_k   = (lane >> 4) << 3;
    const int b_row = (lane & 7) + ((lane >> 4) << 3);
    const int b_k   = ((lane >> 3) & 1) << 3;

    if (tid < 64) { sba[tid] = ba1[d0 + tid]; sbb[tid] = bb1[d0 + tid]; swc[tid] = Wc1[d0 + tid]; }
    if (tid < 128) sA[tid] = 0.0f;

    float acca[4][2][4], accg[4][2][4];
#pragma unroll
    for (int mi = 0; mi < 4; mi++)
#pragma unroll
        for (int ni = 0; ni < 2; ni++)
#pragma unroll
            for (int c = 0; c < 4; c++) { acca[mi][ni][c] = 0.0f; accg[mi][ni][c] = 0.0f; }

    auto load_slab = [&](int kt, int st) {
        const int k0 = kt * 32;
        const uint32_t sb = ub + st * STAGE_B;
#pragma unroll
        for (int i = 0; i < 2; i++) {
            int idx = i * 256 + tid;
            int row = idx >> 2, ch = idx & 3;
            cp16(sb + row * ROW_B + ch * 16,
                 g_x16 + (size_t)(m0 + row) * IDIM + k0 + ch * 8);
        }
#pragma unroll
        for (int i = 0; i < 2; i++) {
            int idx = i * 256 + tid;
            int row = idx >> 2, ch = idx & 3;
            if (row < 64) {
                cp16(sb + 10240 + row * ROW_B + ch * 16,
                     g_Wa16 + (size_t)(d0 + row) * IDIM + k0 + ch * 8);
            } else {
                int r2 = row - 64;
                cp16(sb + 15360 + r2 * ROW_B + ch * 16,
                     g_Wb16 + (size_t)(d0 + r2) * IDIM + k0 + ch * 8);
            }
        }
    };

    load_slab(0, 0); CP_COMMIT();
    load_slab(1, 1); CP_COMMIT();
    load_slab(2, 2); CP_COMMIT();
    load_slab(3, 3); CP_COMMIT();

    for (int p = 0; p < 8; p++) {
        if (p < 7) { CP_WAIT2(); } else { CP_WAIT0(); }
        __syncthreads();
#pragma unroll
        for (int q = 0; q < 2; q++) {
            const uint32_t sax = ub + ((2 * p + q) & 3) * STAGE_B;
            const uint32_t sba_ = sax + 10240;
            const uint32_t sbb_ = sax + 15360;
#pragma unroll
            for (int ks = 0; ks < 2; ks++) {
                uint32_t af[4][4], ba_[2][2], bb_[2][2];
#pragma unroll
                for (int mi = 0; mi < 4; mi++)
                    ldsm_x4(af[mi], sax + (wm + mi * 16 + a_row) * ROW_B + (ks * 16 + a_k) * 2);
                ldsm_x4(&ba_[0][0], sba_ + (wn + b_row) * ROW_B + (ks * 16 + b_k) * 2);
                ldsm_x4(&bb_[0][0], sbb_ + (wn + b_row) * ROW_B + (ks * 16 + b_k) * 2);
#pragma unroll
                for (int mi = 0; mi < 4; mi++)
#pragma unroll
                    for (int ni = 0; ni < 2; ni++) {
                        mma_f16(acca[mi][ni], af[mi], ba_[ni]);
                        mma_f16(accg[mi][ni], af[mi], bb_[ni]);
                    }
            }
        }
        __syncthreads();
        if (p < 6) {
            load_slab(2 * p + 4, (2 * p)     & 3); CP_COMMIT();
            load_slab(2 * p + 5, (2 * p + 1) & 3); CP_COMMIT();
        }
    }

    float rsum[4][2];
#pragma unroll
    for (int mi = 0; mi < 4; mi++) { rsum[mi][0] = 0.0f; rsum[mi][1] = 0.0f; }
#pragma unroll
    for (int mi = 0; mi < 4; mi++)
#pragma unroll
        for (int ni = 0; ni < 2; ni++) {
            int nl = wn + ni * 8 + 2 * tig;
#pragma unroll
            for (int half = 0; half < 2; half++) {
#pragma unroll
                for (int col = 0; col < 2; col++) {
                    int dl = nl + col;
                    float va = tanhf(acca[mi][ni][half * 2 + col] + sba[dl]);
                    float vg = sigmoidf_(accg[mi][ni][half * 2 + col] + sbb[dl]);
                    rsum[mi][half] += va * vg * swc[dl];
                }
            }
        }
#pragma unroll
    for (int mi = 0; mi < 4; mi++)
#pragma unroll
        for (int half = 0; half < 2; half++) {
            float v = rsum[mi][half];
            v += __shfl_xor_sync(0xffffffffu, v, 1);
            v += __shfl_xor_sync(0xffffffffu, v, 2);
            if (tig == 0) atomicAdd(&sA[wm + mi * 16 + gid + half * 8], v);
        }
    __syncthreads();
    if (tid < 128) atomicAdd(&g_A[m0 + tid], sA[tid]);
}

// ---------------- kernel 3: ex = exp(A) (no max-shift: logits tiny, softmax shift-invariant),
//                  segment sum + counts ----------------
__global__ void segsum_kernel(const int* __restrict__ cids) {
    __shared__ float ssum[NSEG];
    __shared__ int   scnt[NSEG];
    const int tid = threadIdx.x;
    if (tid < NSEG) { ssum[tid] = 0.0f; scnt[tid] = 0; }
    __syncthreads();
    for (int m = blockIdx.x * blockDim.x + tid; m < MTOT; m += gridDim.x * blockDim.x) {
        int cid = cids[m];
        cid = min(max(cid, 0), CC);
        int seg = (m >> 14) * NCLUST + cid;
        float ex = expf(g_A[m]);
        g_ex[m] = ex;
        atomicAdd(&ssum[seg], ex);
        atomicAdd(&scnt[seg], 1);
    }
    __syncthreads();
    if (tid < NSEG) {
        atomicAdd(&g_segsum[tid], ssum[tid]);
        atomicAdd(&g_counts[tid], scnt[tid]);
    }
}

// ---------------- kernel 4: cfraw[seg] += w * x[m]  (x in fp16, 128-row chunks) ----------------
__global__ __launch_bounds__(256) void cfeat_kernel(const int* __restrict__ cids) {
    __shared__ float sh[NCLUST][IDIM];
    const int tid = threadIdx.x;
    const int b     = blockIdx.x >> 7;
    const int chunk = blockIdx.x & 127;
    for (int i = tid; i < NCLUST * IDIM; i += 256) ((float*)sh)[i] = 0.0f;
    __syncthreads();
    const int mbase = b * NPB + chunk * 128;
    for (int r = 0; r < 128; r++) {
        int m = mbase + r;
        int cid = cids[m];
        cid = min(max(cid, 0), CC);
        float w = g_ex[m] / g_segsum[b * NCLUST + cid];
        const __half* xr = &g_x16[(size_t)m * IDIM];
        sh[cid][tid]       += w * __half2float(xr[tid]);
        sh[cid][tid + 256] += w * __half2float(xr[tid + 256]);
    }
    __syncthreads();
    for (int c = 0; c < NCLUST; c++) {
        atomicAdd(&g_cfraw[(b * NCLUST + c) * IDIM + tid],       sh[c][tid]);
        atomicAdd(&g_cfraw[(b * NCLUST + c) * IDIM + tid + 256], sh[c][tid + 256]);
    }
}

// ---------------- kernel 5: cfeat + inter-cluster gated logits (merged) ----------------
// block s: cfeat[s] = relu(cfraw[s] @ W_intra + b_intra); then A2[s] via gated attention.
__global__ __launch_bounds__(256) void intra_attn2_kernel(
    const float* __restrict__ Wi, const float* __restrict__ bi,
    const float* __restrict__ Wa2, const float* __restrict__ ba2,
    const float* __restrict__ Wb2, const float* __restrict__ bb2,
    const float* __restrict__ Wc2, const float* __restrict__ bc2)
{
    __shared__ float xr[IDIM];
    __shared__ float cf[IDIM];
    __shared__ float red[256];
    const int s = blockIdx.x, tid = threadIdx.x;
    xr[tid]       = g_cfraw[s * IDIM + tid];
    xr[tid + 256] = g_cfraw[s * IDIM + tid + 256];
    __syncthreads();
#pragma unroll
    for (int jj = 0; jj < 2; jj++) {
        int j = tid + jj * 256;
        float acc = bi[j];
        for (int k = 0; k < IDIM; k++) acc += xr[k] * Wi[(size_t)k * IDIM + j];
        float v = fmaxf(acc, 0.0f);
        cf[j] = v;
        g_cfeat[s * IDIM + j] = v;
    }
    __syncthreads();
    float aa = ba2[tid], bb = bb2[tid];
    for (int k = 0; k < IDIM; k++) {
        float xv = cf[k];
        aa += xv * Wa2[(size_t)k * DDIM + tid];
        bb += xv * Wb2[(size_t)k * DDIM + tid];
    }
    red[tid] = tanhf(aa) * sigmoidf_(bb) * Wc2[tid];
    __syncthreads();
    for (int off = 128; off > 0; off >>= 1) {
        if (tid < off) red[tid] += red[tid + off];
        __syncthreads();
    }
    if (tid == 0)
        g_A2[s] = (g_counts[s] > 0) ? (red[0] + bc2[0]) : -1e30f;
}

// ---------------- kernel 6: per-batch softmax, pooling, classifier ----------------
__global__ __launch_bounds__(256) void final_kernel(
    const float* __restrict__ Wint, const float* __restrict__ bint,
    const float* __restrict__ Wcls, const float* __restrict__ bcls,
    float* __restrict__ out)
{
    __shared__ float sWs[NCLUST];
    __shared__ float sl[IDIM];
    __shared__ float st2[256];
    __shared__ float red[256];
    const int b = blockIdx.x, tid = threadIdx.x;

    if (tid == 0) {
        float mx = -1e30f;
        for (int c = 0; c < NCLUST; c++) mx = fmaxf(mx, g_A2[b * NCLUST + c]);
        float e[NCLUST]; float sum = 0.0f;
        for (int c = 0; c < NCLUST; c++) { e[c] = expf(g_A2[b * NCLUST + c] - mx); sum += e[c]; }
        for (int c = 0; c < NCLUST; c++) sWs[c] = e[c] / sum;
    }
    __syncthreads();

#pragma unroll
    for (int jj = 0; jj < 2; jj++) {
        int j = tid + jj * 256;
        float s = 0.0f;
        for (int c = 0; c < NCLUST; c++)
            s += sWs[c] * g_cfeat[(b * NCLUST + c) * IDIM + j];
        sl[j] = s;
    }
    __syncthreads();

    float acc = bint[tid];
    for (int k = 0; k < IDIM; k++) acc += sl[k] * Wint[(size_t)k * 256 + tid];
    st2[tid] = fmaxf(acc, 0.0f);
    __syncthreads();

    red[tid] = st2[tid] * Wcls[tid * 2 + 0];
    __syncthreads();
    for (int off = 128; off > 0; off >>= 1) {
        if (tid < off) red[tid] += red[tid + off];
        __syncthreads();
    }
    if (tid == 0) out[b * 2 + 0] = red[0] + bcls[0];
    __syncthreads();

    red[tid] = st2[tid] * Wcls[tid * 2 + 1];
    __syncthreads();
    for (int off = 128; off > 0; off >>= 1) {
        if (tid < off) red[tid] += red[tid + off];
        __syncthreads();
    }
    if (tid == 0) out[b * 2 + 1] = red[0] + bcls[1];
}

// ---------------- launch ----------------
extern "C" void kernel_launch(void* const* d_in, const int* in_sizes, int n_in,
                              void* d_out, int out_size)
{
    const float* h       = (const float*)d_in[0];
    const int*   cids    = (const int*)  d_in[1];
    const float* emb     = (const float*)d_in[2];
    const float* W_fuse  = (const float*)d_in[3];
    const float* b_fuse  = (const float*)d_in[4];
    const float* Wa1     = (const float*)d_in[5];
    const float* ba1     = (const float*)d_in[6];
    const float* Wb1     = (const float*)d_in[7];
    const float* bb1     = (const float*)d_in[8];
    const float* Wc1     = (const float*)d_in[9];
    // d_in[10] = bc1 (softmax-invariant, dropped)
    const float* W_intra = (const float*)d_in[11];
    const float* b_intra = (const float*)d_in[12];
    const float* Wa2     = (const float*)d_in[13];
    const float* ba2     = (const float*)d_in[14];
    const float* Wb2     = (const float*)d_in[15];
    const float* bb2     = (const float*)d_in[16];
    const float* Wc2     = (const float*)d_in[17];
    const float* bc2     = (const float*)d_in[18];
    const float* W_inter = (const float*)d_in[19];
    const float* b_inter = (const float*)d_in[20];
    const float* W_cls   = (const float*)d_in[21];
    const float* b_cls   = (const float*)d_in[22];
    float* out = (float*)d_out;

    // unconditional host attr sets (no static guards; capture-safe; idempotent)
    cudaFuncSetAttribute(fuse_f16_kernel,  cudaFuncAttributeMaxDynamicSharedMemorySize, F_DSMEM);
    cudaFuncSetAttribute(attn1_f16_kernel, cudaFuncAttributeMaxDynamicSharedMemorySize, A_DSMEM);

    prep_all_kernel<<<256, 256>>>(W_fuse, b_fuse, emb, Wa1, Wb1);
    fuse_f16_kernel<<<dim3(IDIM / 128, MTOT / 128), 256, F_DSMEM>>>(h, cids);
    attn1_f16_kernel<<<dim3(DDIM / 64, MTOT / 128), 256, A_DSMEM>>>(ba1, bb1, Wc1);
    segsum_kernel<<<256, 256>>>(cids);
    cfeat_kernel<<<BATCH * 128, 256>>>(cids);
    intra_attn2_kernel<<<NSEG, 256>>>(W_intra, b_intra, Wa2, ba2, Wb2, bb2, Wc2, bc2);
    final_kernel<<<BATCH, 256>>>(W_inter, b_inter, W_cls, b_cls, out);
}